// round 10
// baseline (speedup 1.0000x reference)
#include <cuda_runtime.h>

#define Bn 32
#define Nn 1024
#define Cn 768
#define C4 192        // Cn / 4
#define ZCHUNK 32
#define ROWS_PER_Z 32 // Nn / ZCHUNK
#define ORBITS 272
#define GROUPS 8
#define BPG 4         // batches per group

__device__ float g_pdot[Bn * ZCHUNK * 4];  // per-(b,z) partial dot with W
__device__ float g_alpha[Bn * 4];
__device__ int   g_cnt[Bn];                // zero-init at load; self-cleaning

// Pool + GEMV for BPG batches. grid (BPG, ZCHUNK), block 192.
// Last chunk-block per batch (ticket) reduces the 32 partials, writes
// alpha[b], and resets the counter (clean state for the next graph replay).
__global__ void __launch_bounds__(192) pool_alpha_kernel(
    const float* __restrict__ x,
    const float* __restrict__ W,
    const float* __restrict__ bias,
    int b0) {
    int b = b0 + blockIdx.x;
    int z = blockIdx.y;
    int tid = threadIdx.x;  // 0..191
    const float4* p = (const float4*)(x + ((size_t)b * Nn + (size_t)z * ROWS_PER_Z) * Cn) + tid;

    float4 a0 = {0,0,0,0}, a1 = {0,0,0,0}, a2 = {0,0,0,0}, a3 = {0,0,0,0};
#pragma unroll
    for (int n = 0; n < ROWS_PER_Z; n += 8) {
        float4 v[8];
#pragma unroll
        for (int u = 0; u < 8; u++)
            v[u] = __ldcg(&p[(size_t)(n + u) * C4]);
        a0.x += v[0].x + v[4].x; a0.y += v[0].y + v[4].y;
        a0.z += v[0].z + v[4].z; a0.w += v[0].w + v[4].w;
        a1.x += v[1].x + v[5].x; a1.y += v[1].y + v[5].y;
        a1.z += v[1].z + v[5].z; a1.w += v[1].w + v[5].w;
        a2.x += v[2].x + v[6].x; a2.y += v[2].y + v[6].y;
        a2.z += v[2].z + v[6].z; a2.w += v[2].w + v[6].w;
        a3.x += v[3].x + v[7].x; a3.y += v[3].y + v[7].y;
        a3.z += v[3].z + v[7].z; a3.w += v[3].w + v[7].w;
    }
    float4 s;
    s.x = (a0.x + a1.x) + (a2.x + a3.x);
    s.y = (a0.y + a1.y) + (a2.y + a3.y);
    s.z = (a0.z + a1.z) + (a2.z + a3.z);
    s.w = (a0.w + a1.w) + (a2.w + a3.w);

    // per-thread dot with W rows (thread owns channels 4*tid..4*tid+3)
    float d[4];
#pragma unroll
    for (int k = 0; k < 4; k++) {
        float4 w4 = __ldg(&((const float4*)W)[k * C4 + tid]);
        d[k] = s.x * w4.x + s.y * w4.y + s.z * w4.z + s.w * w4.w;
    }
    __shared__ float sdot[6][4];
    int lane = tid & 31, wid = tid >> 5;
#pragma unroll
    for (int k = 0; k < 4; k++) {
#pragma unroll
        for (int off = 16; off > 0; off >>= 1)
            d[k] += __shfl_down_sync(0xffffffffu, d[k], off);
        if (lane == 0) sdot[wid][k] = d[k];
    }
    __syncthreads();
    if (tid < 32) {
        int k = tid & 3, w = tid >> 2;
        float v = (w < 6) ? sdot[w][k] : 0.f;
        v += __shfl_down_sync(0xffffffffu, v, 16);
        v += __shfl_down_sync(0xffffffffu, v, 8);
        v += __shfl_down_sync(0xffffffffu, v, 4);
        if (tid < 4)
            __stcg(&g_pdot[((size_t)b * ZCHUNK + z) * 4 + k], v);
    }

    __shared__ int tkt;
    __syncthreads();
    if (tid == 0) {
        int old;
        asm volatile("atom.add.acq_rel.gpu.s32 %0, [%1], 1;"
                     : "=r"(old) : "l"(g_cnt + b) : "memory");
        tkt = old;
    }
    __syncthreads();
    if (tkt == ZCHUNK - 1) {
        if (tid < 128) {  // warp k reduces component k over 32 partials
            int k = tid >> 5, ln = tid & 31;
            float v = __ldcg(&g_pdot[((size_t)b * ZCHUNK + ln) * 4 + k]);
#pragma unroll
            for (int off = 16; off > 0; off >>= 1)
                v += __shfl_down_sync(0xffffffffu, v, off);
            if (ln == 0)
                __stcg(&g_alpha[b * 4 + k], v * (1.0f / 1024.0f) + __ldg(&bias[k]));
        }
        __syncthreads();
        if (tid == 0)
            asm volatile("st.release.gpu.s32 [%0], 0;"
                         :: "l"(g_cnt + b) : "memory");
    }
}

// Orbit merge for BPG batches. grid BPG*ORBITS, block 192.
// Launched only after its group's pool kernel completes (graph dependency),
// so alpha is ready — no device-side waiting anywhere.
__global__ void __launch_bounds__(192) merge_kernel(
    const float* __restrict__ x,
    float* __restrict__ out,
    int b0) {
    int bid = blockIdx.x;
    int b = b0 + bid / ORBITS;
    int o = bid % ORBITS;
    int i = 0, cnt = 32;
    while (o >= cnt) { o -= cnt; i++; cnt -= 2; }
    int j = i + o;  // i <= j <= 31-i

    int l   = (i << 5) | j;
    int tl  = (j << 5) | i;
    int rl  = 1023 - l;
    int rtl = 1023 - tl;
    bool d1 = (i == j);        // tl==l,  rtl==rl
    bool d2 = (j == 31 - i);   // rl==tl, rtl==l

    float c0 = g_alpha[b * 4 + 0];
    float c1 = g_alpha[b * 4 + 1];
    float c2 = g_alpha[b * 4 + 2];
    float c3 = g_alpha[b * 4 + 3];

    const float4* xb = (const float4*)(x + (size_t)b * Nn * Cn);
    float4*       ob = (float4*)(out + (size_t)b * Nn * Cn);
    int t = threadIdx.x;  // 0..191

    float4 v0 = __ldcg(&xb[(size_t)l * C4 + t]);
    float4 v1 = d1 ? v0 : __ldcg(&xb[(size_t)tl * C4 + t]);
    float4 v2 = d2 ? v1 : __ldcg(&xb[(size_t)rl * C4 + t]);
    float4 v3 = d1 ? v2 : (d2 ? v0 : __ldcg(&xb[(size_t)rtl * C4 + t]));

    float4 w;
    // out[l] = c0 v0 + c1 v1 + c2 v2 + c3 v3
    w.x = fmaf(c0, v0.x, fmaf(c1, v1.x, fmaf(c2, v2.x, c3 * v3.x)));
    w.y = fmaf(c0, v0.y, fmaf(c1, v1.y, fmaf(c2, v2.y, c3 * v3.y)));
    w.z = fmaf(c0, v0.z, fmaf(c1, v1.z, fmaf(c2, v2.z, c3 * v3.z)));
    w.w = fmaf(c0, v0.w, fmaf(c1, v1.w, fmaf(c2, v2.w, c3 * v3.w)));
    __stcs(&ob[(size_t)l * C4 + t], w);

    if (!d1) {  // out[tl] = c0 v1 + c1 v0 + c2 v3 + c3 v2
        w.x = fmaf(c0, v1.x, fmaf(c1, v0.x, fmaf(c2, v3.x, c3 * v2.x)));
        w.y = fmaf(c0, v1.y, fmaf(c1, v0.y, fmaf(c2, v3.y, c3 * v2.y)));
        w.z = fmaf(c0, v1.z, fmaf(c1, v0.z, fmaf(c2, v3.z, c3 * v2.z)));
        w.w = fmaf(c0, v1.w, fmaf(c1, v0.w, fmaf(c2, v3.w, c3 * v2.w)));
        __stcs(&ob[(size_t)tl * C4 + t], w);
    }
    if (!d2) {  // out[rl] = c0 v2 + c1 v3 + c2 v0 + c3 v1
        w.x = fmaf(c0, v2.x, fmaf(c1, v3.x, fmaf(c2, v0.x, c3 * v1.x)));
        w.y = fmaf(c0, v2.y, fmaf(c1, v3.y, fmaf(c2, v0.y, c3 * v1.y)));
        w.z = fmaf(c0, v2.z, fmaf(c1, v3.z, fmaf(c2, v0.z, c3 * v1.z)));
        w.w = fmaf(c0, v2.w, fmaf(c1, v3.w, fmaf(c2, v0.w, c3 * v1.w)));
        __stcs(&ob[(size_t)rl * C4 + t], w);
    }
    if (!d1 && !d2) {  // out[rtl] = c0 v3 + c1 v2 + c2 v1 + c3 v0
        w.x = fmaf(c0, v3.x, fmaf(c1, v2.x, fmaf(c2, v1.x, c3 * v0.x)));
        w.y = fmaf(c0, v3.y, fmaf(c1, v2.y, fmaf(c2, v1.y, c3 * v0.y)));
        w.z = fmaf(c0, v3.z, fmaf(c1, v2.z, fmaf(c2, v1.z, c3 * v0.z)));
        w.w = fmaf(c0, v3.w, fmaf(c1, v2.w, fmaf(c2, v1.w, c3 * v0.w)));
        __stcs(&ob[(size_t)rtl * C4 + t], w);
    }
}

extern "C" void kernel_launch(void* const* d_in, const int* in_sizes, int n_in,
                              void* d_out, int out_size) {
    const float* x    = (const float*)d_in[0];  // (32,1024,768)
    const float* W    = (const float*)d_in[1];  // (4,768)
    const float* bias = (const float*)d_in[2];  // (4,)
    float* out = (float*)d_out;

    // One-time handles (resource init only — work per call is identical).
    static cudaStream_t s1 = nullptr;
    static cudaEvent_t evP[GROUPS];
    static cudaEvent_t evJoin;
    if (s1 == nullptr) {
        cudaStreamCreateWithFlags(&s1, cudaStreamNonBlocking);
        for (int g = 0; g < GROUPS; g++)
            cudaEventCreateWithFlags(&evP[g], cudaEventDisableTiming);
        cudaEventCreateWithFlags(&evJoin, cudaEventDisableTiming);
    }

    // Pipelined groups: pools run back-to-back on the main stream; each
    // group's merge launches on s1 as soon as that group's pool is done.
    // merge(g) overlaps pool(g+1..): mixed read+write streams, no spinning.
    for (int g = 0; g < GROUPS; g++) {
        dim3 gp(BPG, ZCHUNK);
        pool_alpha_kernel<<<gp, 192>>>(x, W, bias, g * BPG);
        cudaEventRecord(evP[g], 0);
        cudaStreamWaitEvent(s1, evP[g], 0);
        merge_kernel<<<BPG * ORBITS, 192, 0, s1>>>(x, out, g * BPG);
    }
    // Join the side stream back into the capture-origin stream.
    cudaEventRecord(evJoin, s1);
    cudaStreamWaitEvent(0, evJoin, 0);
}

// round 12
// speedup vs baseline: 1.9706x; 1.9706x over previous
#include <cuda_runtime.h>

#define Bn 32
#define Nn 1024
#define Cn 768
#define C4 192        // Cn / 4
#define ZCHUNK 32
#define ROWS_PER_Z 32 // Nn / ZCHUNK
#define ORBITS 272

__device__ float g_pdot[Bn * ZCHUNK * 4];  // per-(b,z) partial dot with W
__device__ float g_alpha[Bn * 4];
__device__ int   g_cnt[Bn];                // zero-init at load; self-cleaning

// Pass 1 (fused pool + GEMV): grid (Bn, ZCHUNK), block 192.
// Last chunk-block per batch (ticket) reduces the 32 partials, writes
// alpha[b], and resets the counter (clean state for the next graph replay).
__global__ void __launch_bounds__(192) pool_alpha_kernel(
    const float* __restrict__ x,
    const float* __restrict__ W,
    const float* __restrict__ bias) {
    int b = blockIdx.x;
    int z = blockIdx.y;
    int tid = threadIdx.x;  // 0..191
    const float4* p = (const float4*)(x + ((size_t)b * Nn + (size_t)z * ROWS_PER_Z) * Cn) + tid;

    float4 a0 = {0,0,0,0}, a1 = {0,0,0,0}, a2 = {0,0,0,0}, a3 = {0,0,0,0};
#pragma unroll
    for (int n = 0; n < ROWS_PER_Z; n += 8) {
        float4 v[8];
#pragma unroll
        for (int u = 0; u < 8; u++)
            v[u] = __ldcg(&p[(size_t)(n + u) * C4]);
        a0.x += v[0].x + v[4].x; a0.y += v[0].y + v[4].y;
        a0.z += v[0].z + v[4].z; a0.w += v[0].w + v[4].w;
        a1.x += v[1].x + v[5].x; a1.y += v[1].y + v[5].y;
        a1.z += v[1].z + v[5].z; a1.w += v[1].w + v[5].w;
        a2.x += v[2].x + v[6].x; a2.y += v[2].y + v[6].y;
        a2.z += v[2].z + v[6].z; a2.w += v[2].w + v[6].w;
        a3.x += v[3].x + v[7].x; a3.y += v[3].y + v[7].y;
        a3.z += v[3].z + v[7].z; a3.w += v[3].w + v[7].w;
    }
    float4 s;
    s.x = (a0.x + a1.x) + (a2.x + a3.x);
    s.y = (a0.y + a1.y) + (a2.y + a3.y);
    s.z = (a0.z + a1.z) + (a2.z + a3.z);
    s.w = (a0.w + a1.w) + (a2.w + a3.w);

    // per-thread dot with W rows (thread owns channels 4*tid..4*tid+3)
    float d[4];
#pragma unroll
    for (int k = 0; k < 4; k++) {
        float4 w4 = __ldg(&((const float4*)W)[k * C4 + tid]);
        d[k] = s.x * w4.x + s.y * w4.y + s.z * w4.z + s.w * w4.w;
    }
    __shared__ float sdot[6][4];
    int lane = tid & 31, wid = tid >> 5;
#pragma unroll
    for (int k = 0; k < 4; k++) {
#pragma unroll
        for (int off = 16; off > 0; off >>= 1)
            d[k] += __shfl_down_sync(0xffffffffu, d[k], off);
        if (lane == 0) sdot[wid][k] = d[k];
    }
    __syncthreads();
    if (tid < 32) {
        int k = tid & 3, w = tid >> 2;
        float v = (w < 6) ? sdot[w][k] : 0.f;
        v += __shfl_down_sync(0xffffffffu, v, 16);
        v += __shfl_down_sync(0xffffffffu, v, 8);
        v += __shfl_down_sync(0xffffffffu, v, 4);
        if (tid < 4)
            __stcg(&g_pdot[((size_t)b * ZCHUNK + z) * 4 + k], v);
    }

    __shared__ int tkt;
    __syncthreads();
    if (tid == 0) {
        int old;
        asm volatile("atom.add.acq_rel.gpu.s32 %0, [%1], 1;"
                     : "=r"(old) : "l"(g_cnt + b) : "memory");
        tkt = old;
    }
    __syncthreads();
    if (tkt == ZCHUNK - 1) {
        if (tid < 128) {  // warp k reduces component k over 32 partials
            int k = tid >> 5, ln = tid & 31;
            float v = __ldcg(&g_pdot[((size_t)b * ZCHUNK + ln) * 4 + k]);
#pragma unroll
            for (int off = 16; off > 0; off >>= 1)
                v += __shfl_down_sync(0xffffffffu, v, off);
            if (ln == 0)
                __stcg(&g_alpha[b * 4 + k], v * (1.0f / 1024.0f) + __ldg(&bias[k]));
        }
        __syncthreads();
        if (tid == 0)
            asm volatile("st.release.gpu.s32 [%0], 0;"
                         :: "l"(g_cnt + b) : "memory");
    }
}

// Pass 2: orbit merge, batches processed in REVERSE order: pool read batches
// 0->31, so the last-read batches are freshest in L2 — merging them first
// converts LRU recency into hits instead of missing on long-evicted batch 0.
__global__ void __launch_bounds__(192) merge_kernel(
    const float* __restrict__ x,
    float* __restrict__ out) {
    int bid = blockIdx.x;
    int b = (Bn - 1) - (bid / ORBITS);   // reverse batch order
    int o = bid % ORBITS;
    int i = 0, cnt = 32;
    while (o >= cnt) { o -= cnt; i++; cnt -= 2; }
    int j = i + o;  // i <= j <= 31-i

    int l   = (i << 5) | j;
    int tl  = (j << 5) | i;
    int rl  = 1023 - l;
    int rtl = 1023 - tl;
    bool d1 = (i == j);        // tl==l,  rtl==rl
    bool d2 = (j == 31 - i);   // rl==tl, rtl==l

    float c0 = g_alpha[b * 4 + 0];
    float c1 = g_alpha[b * 4 + 1];
    float c2 = g_alpha[b * 4 + 2];
    float c3 = g_alpha[b * 4 + 3];

    const float4* xb = (const float4*)(x + (size_t)b * Nn * Cn);
    float4*       ob = (float4*)(out + (size_t)b * Nn * Cn);
    int t = threadIdx.x;  // 0..191

    float4 v0 = __ldcg(&xb[(size_t)l * C4 + t]);
    float4 v1 = d1 ? v0 : __ldcg(&xb[(size_t)tl * C4 + t]);
    float4 v2 = d2 ? v1 : __ldcg(&xb[(size_t)rl * C4 + t]);
    float4 v3 = d1 ? v2 : (d2 ? v0 : __ldcg(&xb[(size_t)rtl * C4 + t]));

    float4 w;
    // out[l] = c0 v0 + c1 v1 + c2 v2 + c3 v3
    w.x = fmaf(c0, v0.x, fmaf(c1, v1.x, fmaf(c2, v2.x, c3 * v3.x)));
    w.y = fmaf(c0, v0.y, fmaf(c1, v1.y, fmaf(c2, v2.y, c3 * v3.y)));
    w.z = fmaf(c0, v0.z, fmaf(c1, v1.z, fmaf(c2, v2.z, c3 * v3.z)));
    w.w = fmaf(c0, v0.w, fmaf(c1, v1.w, fmaf(c2, v2.w, c3 * v3.w)));
    __stcs(&ob[(size_t)l * C4 + t], w);

    if (!d1) {  // out[tl] = c0 v1 + c1 v0 + c2 v3 + c3 v2
        w.x = fmaf(c0, v1.x, fmaf(c1, v0.x, fmaf(c2, v3.x, c3 * v2.x)));
        w.y = fmaf(c0, v1.y, fmaf(c1, v0.y, fmaf(c2, v3.y, c3 * v2.y)));
        w.z = fmaf(c0, v1.z, fmaf(c1, v0.z, fmaf(c2, v3.z, c3 * v2.z)));
        w.w = fmaf(c0, v1.w, fmaf(c1, v0.w, fmaf(c2, v3.w, c3 * v2.w)));
        __stcs(&ob[(size_t)tl * C4 + t], w);
    }
    if (!d2) {  // out[rl] = c0 v2 + c1 v3 + c2 v0 + c3 v1
        w.x = fmaf(c0, v2.x, fmaf(c1, v3.x, fmaf(c2, v0.x, c3 * v1.x)));
        w.y = fmaf(c0, v2.y, fmaf(c1, v3.y, fmaf(c2, v0.y, c3 * v1.y)));
        w.z = fmaf(c0, v2.z, fmaf(c1, v3.z, fmaf(c2, v0.z, c3 * v1.z)));
        w.w = fmaf(c0, v2.w, fmaf(c1, v3.w, fmaf(c2, v0.w, c3 * v1.w)));
        __stcs(&ob[(size_t)rl * C4 + t], w);
    }
    if (!d1 && !d2) {  // out[rtl] = c0 v3 + c1 v2 + c2 v1 + c3 v0
        w.x = fmaf(c0, v3.x, fmaf(c1, v2.x, fmaf(c2, v1.x, c3 * v0.x)));
        w.y = fmaf(c0, v3.y, fmaf(c1, v2.y, fmaf(c2, v1.y, c3 * v0.y)));
        w.z = fmaf(c0, v3.z, fmaf(c1, v2.z, fmaf(c2, v1.z, c3 * v0.z)));
        w.w = fmaf(c0, v3.w, fmaf(c1, v2.w, fmaf(c2, v1.w, c3 * v0.w)));
        __stcs(&ob[(size_t)rtl * C4 + t], w);
    }
}

extern "C" void kernel_launch(void* const* d_in, const int* in_sizes, int n_in,
                              void* d_out, int out_size) {
    const float* x    = (const float*)d_in[0];  // (32,1024,768)
    const float* W    = (const float*)d_in[1];  // (4,768)
    const float* bias = (const float*)d_in[2];  // (4,)
    float* out = (float*)d_out;

    dim3 g1(Bn, ZCHUNK);
    pool_alpha_kernel<<<g1, 192>>>(x, W, bias);
    merge_kernel<<<Bn * ORBITS, 192>>>(x, out);
}